// round 1
// baseline (speedup 1.0000x reference)
#include <cuda_runtime.h>
#include <cuda_bf16.h>
#include <math.h>

// ---------------- problem constants ----------------
constexpr int CB    = 2;
constexpr int CQ    = 1024;
constexpr int CHID  = 2048;
constexpr int CNH   = 32;
constexpr int CNKV  = 8;
constexpr int CHD   = 64;
constexpr int CG    = 4;      // GROUPS = NH/NKV
constexpr int CKB   = 512;
constexpr int CTOPK = 100;
#define SCALE_F  0.125f                 // 1/sqrt(64)
#define KB_BIAS  1.6331544f             // log(512) - log(100)

// ---------------- scratch (device globals; no cudaMalloc allowed) ----------------
__device__ float g_q   [CB*CQ*CNH*CHD];    // roped Q        [B,Q,NH,HD]
__device__ float g_kbq [CB*CQ*CNH*CHD];    // KB query (no rope)
__device__ float g_k   [CB*CQ*CNKV*CHD];   // roped K        [B,Q,NKV,HD]
__device__ float g_v   [CB*CQ*CNKV*CHD];
__device__ float g_kbk [CB*CKB*CNKV*CHD];  // [B,KB,NKV,HD]
__device__ float g_kbv [CB*CKB*CNKV*CHD];
__device__ float g_attn[CB*CQ*CNH*CHD];    // attention output, [B,Q,NH*HD]
__device__ float g_qsum_part[CB*16*CNKV*CHD];
__device__ float g_qsum[CB*CNKV*CHD];
__device__ float g_scores[CB*CKB];
__device__ int   g_topidx[CB*CTOPK];

// ---------------- generic tiled SGEMM: C[M,N] = A[M,K] @ B[K,N] (row-major, all dims divisible) ----------------
template<int BM, int BN, int BK, int TM, int TN>
__global__ __launch_bounds__((BM/TM)*(BN/TN))
void gemm_kernel(const float* __restrict__ A, const float* __restrict__ Bm,
                 float* __restrict__ C, int M, int N, int K) {
    constexpr int TX = BN / TN;
    constexpr int TY = BM / TM;
    constexpr int NT = TX * TY;
    __shared__ __align__(16) float As[BK][BM + 4];   // transposed A tile: As[k][m]
    __shared__ __align__(16) float Bs[BK][BN];

    const int tid = threadIdx.x;
    const int tx = tid % TX, ty = tid / TX;
    const int rb = blockIdx.y * BM, cb = blockIdx.x * BN;

    float acc[TM][TN] = {};

    for (int k0 = 0; k0 < K; k0 += BK) {
        #pragma unroll
        for (int i = tid; i < BM * BK; i += NT) {
            int m = i / BK, kk = i % BK;
            As[kk][m] = A[(size_t)(rb + m) * K + k0 + kk];
        }
        #pragma unroll
        for (int i = tid; i < BK * BN; i += NT) {
            int kk = i / BN, n = i % BN;
            Bs[kk][n] = Bm[(size_t)(k0 + kk) * N + cb + n];
        }
        __syncthreads();
        #pragma unroll
        for (int kk = 0; kk < BK; kk++) {
            float a[TM], b[TN];
            #pragma unroll
            for (int i = 0; i < TM; i += 4) {
                float4 t = *(const float4*)&As[kk][ty * TM + i];
                a[i] = t.x; a[i+1] = t.y; a[i+2] = t.z; a[i+3] = t.w;
            }
            #pragma unroll
            for (int j = 0; j < TN; j += 4) {
                float4 t = *(const float4*)&Bs[kk][tx * TN + j];
                b[j] = t.x; b[j+1] = t.y; b[j+2] = t.z; b[j+3] = t.w;
            }
            #pragma unroll
            for (int i = 0; i < TM; i++)
                #pragma unroll
                for (int j = 0; j < TN; j++)
                    acc[i][j] = fmaf(a[i], b[j], acc[i][j]);
        }
        __syncthreads();
    }
    #pragma unroll
    for (int i = 0; i < TM; i++)
        #pragma unroll
        for (int j = 0; j < TN; j += 4) {
            float4 v = make_float4(acc[i][j], acc[i][j+1], acc[i][j+2], acc[i][j+3]);
            *(float4*)&C[(size_t)(rb + ty * TM + i) * N + cb + tx * TN + j] = v;
        }
}

// ---------------- RoPE in place on [B*Q, nheads*64] ----------------
__global__ void rope_kernel(float* __restrict__ x, const int* __restrict__ pos_ids,
                            const float* __restrict__ cosT, const float* __restrict__ sinT,
                            int nheads, int total) {
    int idx = blockIdx.x * blockDim.x + threadIdx.x;
    if (idx >= total) return;
    int d   = idx & 31;
    int h   = (idx >> 5) % nheads;
    int row = idx / (32 * nheads);
    int pos = pos_ids[row];
    float c1 = cosT[pos * 64 + d],      s1 = sinT[pos * 64 + d];
    float c2 = cosT[pos * 64 + d + 32], s2 = sinT[pos * 64 + d + 32];
    float* p = x + (size_t)row * nheads * 64 + h * 64;
    float x1 = p[d], x2 = p[d + 32];
    p[d]      = x1 * c1 - x2 * s1;
    p[d + 32] = x2 * c2 + x1 * s2;
}

// ---------------- KB selection: qsum over (q, group) ----------------
__global__ void qsum_partial_kernel() {
    // grid (B, 16 chunks of 64 queries), 512 threads = one per (kh,d) column
    int b  = blockIdx.x, ch = blockIdx.y;
    int c  = threadIdx.x;             // 0..511
    int kh = c / CHD, dd = c % CHD;
    float s = 0.f;
    for (int q = ch * 64; q < ch * 64 + 64; q++) {
        const float* row = g_kbq + (size_t)(b * CQ + q) * (CNH * CHD);
        #pragma unroll
        for (int g = 0; g < CG; g++) s += row[(kh * CG + g) * CHD + dd];
    }
    g_qsum_part[(b * 16 + ch) * 512 + c] = s;
}

__global__ void qsum_combine_kernel() {
    int b = blockIdx.x, c = threadIdx.x;
    float s = 0.f;
    #pragma unroll
    for (int ch = 0; ch < 16; ch++) s += g_qsum_part[(b * 16 + ch) * 512 + c];
    g_qsum[b * 512 + c] = s;
}

__global__ void scores_kernel() {
    // one warp per (b, n); scale omitted (positive constant, ranking only)
    int gw = blockIdx.x * 8 + (threadIdx.x >> 5);
    int l  = threadIdx.x & 31;
    int b  = gw >> 9, n = gw & 511;
    const float* kr = g_kbk + (size_t)(b * CKB + n) * (CNKV * CHD);
    const float* qs = g_qsum + b * 512;
    float s = 0.f;
    #pragma unroll
    for (int i = l; i < 512; i += 32) s = fmaf(kr[i], qs[i], s);
    #pragma unroll
    for (int o = 16; o > 0; o >>= 1) s += __shfl_xor_sync(0xffffffffu, s, o);
    if (l == 0) g_scores[b * CKB + n] = s;
}

__global__ void topk_kernel() {
    int b = blockIdx.x;
    __shared__ float sv[CKB];
    __shared__ float cv[16];
    __shared__ int   ci[16];
    int tid = threadIdx.x;            // 512 threads
    sv[tid] = g_scores[b * CKB + tid];
    __syncthreads();
    for (int t = 0; t < CTOPK; t++) {
        float v = sv[tid]; int idx = tid;
        #pragma unroll
        for (int o = 16; o > 0; o >>= 1) {
            float ov = __shfl_xor_sync(0xffffffffu, v, o);
            int   oi = __shfl_xor_sync(0xffffffffu, idx, o);
            if (ov > v || (ov == v && oi < idx)) { v = ov; idx = oi; }
        }
        if ((tid & 31) == 0) { cv[tid >> 5] = v; ci[tid >> 5] = idx; }
        __syncthreads();
        if (tid < 32) {
            float v2 = (tid < 16) ? cv[tid] : -3.0e38f;
            int   i2 = (tid < 16) ? ci[tid] : 0x7fffffff;
            #pragma unroll
            for (int o = 16; o > 0; o >>= 1) {
                float ov = __shfl_xor_sync(0xffffffffu, v2, o);
                int   oi = __shfl_xor_sync(0xffffffffu, i2, o);
                if (ov > v2 || (ov == v2 && oi < i2)) { v2 = ov; i2 = oi; }
            }
            if (tid == 0) { g_topidx[b * CTOPK + t] = i2; sv[i2] = -3.0e38f; }
        }
        __syncthreads();
    }
}

// ---------------- fused flash attention: KB(top-100) keys + causal prefix ----------------
// block = (qtile of 32, head, batch), 256 threads = 8 warps, warp owns 4 query rows,
// lane owns key pair (2l, 2l+1) for scores and dim pair (2l, 2l+1) for output.
__global__ __launch_bounds__(256) void attn_kernel() {
    __shared__ __align__(16) float q_s[32][64];        // 8 KB (scaled)
    __shared__ __align__(16) float kp_s[64 * 66];      // K^T [d][key] padded; reused as P[32][64]
    __shared__ __align__(16) float v_s[64][64];        // V [key][d]

    const int b = blockIdx.z, h = blockIdx.y, qt = blockIdx.x;
    const int kh = h / CG;
    const int tid = threadIdx.x;
    const int w = tid >> 5, l = tid & 31;
    const int q0 = qt * 32;
    const int r0 = w * 4;

    float m[4], lsum[4];
    float2 acc[4];
    #pragma unroll
    for (int r = 0; r < 4; r++) { m[r] = -1e30f; lsum[r] = 0.f; acc[r] = make_float2(0.f, 0.f); }

    for (int ph = 0; ph < 2; ph++) {
        const float* qsrc = ph ? g_q : g_kbq;
        for (int i = tid; i < 32 * 64; i += 256) {
            int r = i >> 6, d = i & 63;
            q_s[r][d] = qsrc[(size_t)(b * CQ + q0 + r) * (CNH * CHD) + h * CHD + d] * SCALE_F;
        }
        __syncthreads();
        const int ntiles = ph ? (q0 + 32 + 63) / 64 : 2;
        for (int t = 0; t < ntiles; t++) {
            // ---- load K/V tile ----
            if (ph == 0) {
                for (int i = tid; i < 64 * 64; i += 256) {
                    int j = i >> 6, d = i & 63;
                    int kg = t * 64 + j;
                    float kv = 0.f, vv = 0.f;
                    if (kg < CTOPK) {
                        int n = g_topidx[b * CTOPK + kg];
                        size_t base = (size_t)(b * CKB + n) * (CNKV * CHD) + kh * CHD + d;
                        kv = g_kbk[base]; vv = g_kbv[base];
                    }
                    kp_s[d * 66 + j] = kv;
                    v_s[j][d] = vv;
                }
            } else {
                for (int i = tid; i < 64 * 64; i += 256) {
                    int j = i >> 6, d = i & 63;
                    int kg = t * 64 + j;
                    size_t base = (size_t)(b * CQ + kg) * (CNKV * CHD) + kh * CHD + d;
                    kp_s[d * 66 + j] = g_k[base];
                    v_s[j][d] = g_v[base];
                }
            }
            __syncthreads();

            // ---- QK^T: 4 rows x 2 keys per lane ----
            float s[4][2] = {};
            #pragma unroll 16
            for (int d = 0; d < 64; d++) {
                float2 kv = *(const float2*)&kp_s[d * 66 + 2 * l];
                #pragma unroll
                for (int r = 0; r < 4; r++) {
                    float qv = q_s[r0 + r][d];
                    s[r][0] = fmaf(qv, kv.x, s[r][0]);
                    s[r][1] = fmaf(qv, kv.y, s[r][1]);
                }
            }
            // ---- bias / mask ----
            const int jg = t * 64 + 2 * l;
            if (ph == 0) {
                #pragma unroll
                for (int r = 0; r < 4; r++) {
                    s[r][0] = (jg     < CTOPK) ? s[r][0] + KB_BIAS : -1e30f;
                    s[r][1] = (jg + 1 < CTOPK) ? s[r][1] + KB_BIAS : -1e30f;
                }
            } else {
                #pragma unroll
                for (int r = 0; r < 4; r++) {
                    int qr = q0 + r0 + r;
                    if (jg     > qr) s[r][0] = -1e30f;
                    if (jg + 1 > qr) s[r][1] = -1e30f;
                }
            }
            // ---- online softmax update ----
            float p[4][2];
            #pragma unroll
            for (int r = 0; r < 4; r++) {
                float mx = fmaxf(s[r][0], s[r][1]);
                #pragma unroll
                for (int o = 16; o > 0; o >>= 1) mx = fmaxf(mx, __shfl_xor_sync(0xffffffffu, mx, o));
                float mnew = fmaxf(m[r], mx);
                float corr = __expf(m[r] - mnew);
                p[r][0] = __expf(s[r][0] - mnew);
                p[r][1] = __expf(s[r][1] - mnew);
                float ps = p[r][0] + p[r][1];
                #pragma unroll
                for (int o = 16; o > 0; o >>= 1) ps += __shfl_xor_sync(0xffffffffu, ps, o);
                lsum[r] = lsum[r] * corr + ps;
                acc[r].x *= corr; acc[r].y *= corr;
                m[r] = mnew;
            }
            __syncthreads();   // all warps finished reading K before P overwrites kp_s
            #pragma unroll
            for (int r = 0; r < 4; r++)
                *(float2*)&kp_s[(r0 + r) * 64 + 2 * l] = make_float2(p[r][0], p[r][1]);
            __syncwarp();
            // ---- P @ V ----
            #pragma unroll 16
            for (int j = 0; j < 64; j++) {
                float2 vv = *(const float2*)&v_s[j][2 * l];
                #pragma unroll
                for (int r = 0; r < 4; r++) {
                    float pj = kp_s[(r0 + r) * 64 + j];
                    acc[r].x = fmaf(pj, vv.x, acc[r].x);
                    acc[r].y = fmaf(pj, vv.y, acc[r].y);
                }
            }
            __syncthreads();   // before next tile load / q reload
        }
    }
    #pragma unroll
    for (int r = 0; r < 4; r++) {
        float inv = 1.f / lsum[r];
        float2 o = make_float2(acc[r].x * inv, acc[r].y * inv);
        *(float2*)&g_attn[(size_t)(b * CQ + q0 + r0 + r) * (CNH * CHD) + h * CHD + 2 * l] = o;
    }
}

// ---------------- launch ----------------
extern "C" void kernel_launch(void* const* d_in, const int* in_sizes, int n_in,
                              void* d_out, int out_size) {
    const float* hs   = (const float*)d_in[0];
    const float* kb   = (const float*)d_in[1];
    const float* Wq   = (const float*)d_in[2];
    const float* Wk   = (const float*)d_in[3];
    const float* Wv   = (const float*)d_in[4];
    const float* Wo   = (const float*)d_in[5];
    const float* Wqn  = (const float*)d_in[6];
    const float* Wkbk = (const float*)d_in[7];
    const float* Wkbv = (const float*)d_in[8];
    const float* cosT = (const float*)d_in[9];
    const float* sinT = (const float*)d_in[10];
    // d_in[11] = attention_mask (pure causal; reproduced analytically)
    const int*   pos  = (const int*)d_in[12];
    float* out = (float*)d_out;

    float *pq, *pkbq, *pk, *pv, *pkbk, *pkbv, *pattn;
    cudaGetSymbolAddress((void**)&pq,    g_q);
    cudaGetSymbolAddress((void**)&pkbq,  g_kbq);
    cudaGetSymbolAddress((void**)&pk,    g_k);
    cudaGetSymbolAddress((void**)&pv,    g_v);
    cudaGetSymbolAddress((void**)&pkbk,  g_kbk);
    cudaGetSymbolAddress((void**)&pkbv,  g_kbv);
    cudaGetSymbolAddress((void**)&pattn, g_attn);

    const int M = CB * CQ;          // 2048
    // projections
    gemm_kernel<128,128,16,8,8><<<dim3(CHID/128, M/128), 256>>>(hs,  Wq,   pq,   M, CHID, CHID);
    gemm_kernel<128,128,16,8,8><<<dim3(CHID/128, M/128), 256>>>(hs,  Wqn,  pkbq, M, CHID, CHID);
    gemm_kernel< 64, 64,16,4,4><<<dim3(512/64,  M/64 ), 256>>>(hs,  Wk,   pk,   M, 512,  CHID);
    gemm_kernel< 64, 64,16,4,4><<<dim3(512/64,  M/64 ), 256>>>(hs,  Wv,   pv,   M, 512,  CHID);
    gemm_kernel< 64, 64,16,4,4><<<dim3(512/64, (CB*CKB)/64), 256>>>(kb, Wkbk, pkbk, CB*CKB, 512, CHID);
    gemm_kernel< 64, 64,16,4,4><<<dim3(512/64, (CB*CKB)/64), 256>>>(kb, Wkbv, pkbv, CB*CKB, 512, CHID);
    // RoPE (q with 32 heads, k with 8 heads)
    {
        int tq = CB * CQ * CNH * 32;
        rope_kernel<<<(tq + 255) / 256, 256>>>(pq, pos, cosT, sinT, CNH, tq);
        int tk = CB * CQ * CNKV * 32;
        rope_kernel<<<(tk + 255) / 256, 256>>>(pk, pos, cosT, sinT, CNKV, tk);
    }
    // KB top-k selection (factored scores — no [B,NH,Q,KB] materialization)
    qsum_partial_kernel<<<dim3(CB, 16), 512>>>();
    qsum_combine_kernel<<<CB, 512>>>();
    scores_kernel<<<(CB * CKB) / 8, 256>>>();
    topk_kernel<<<CB, 512>>>();
    // fused attention
    attn_kernel<<<dim3(CQ / 32, CNH, CB), 256>>>();
    // output projection
    gemm_kernel<128,128,16,8,8><<<dim3(CHID/128, M/128), 256>>>(pattn, Wo, out, M, CHID, CHID);
}